// round 1
// baseline (speedup 1.0000x reference)
#include <cuda_runtime.h>

// Problem constants (shapes fixed by the benchmark instance)
#define W_IN      128
#define UP_FACTOR 8
#define SIZE      (W_IN * UP_FACTOR)   // 1024 interpolated points
#define NTHREADS  128
#define QPT       (SIZE / NTHREADS)    // 8 queries per thread
#define POINT_ORDER_WEIGHT 0.1f

// Deterministic per-CTA partials: x = sum(min_dist * m), y = sum(order_penalty * m),
// z = sum(direct_err * m) [dir==0 CTAs only]
__device__ float4 g_part[1024];

__global__ __launch_bounds__(NTHREADS)
void chamfer_scan_kernel(const float* __restrict__ tgt,
                         const float* __restrict__ pred,
                         const float* __restrict__ vis)
{
    const int n   = blockIdx.x >> 1;
    const int dir = blockIdx.x & 1;
    const int tid = threadIdx.x;

    __shared__ float2   sh_q[SIZE];     // interpolated queries (points2)
    __shared__ float2   sh_c[SIZE];     // NEGATED interpolated candidates (points1)
    __shared__ float    sh_m[SIZE];     // thresholded mask
    __shared__ unsigned sh_idx[SIZE];   // argmin indices
    __shared__ float    sh_red[12];     // warp partials (4 warps x 3 sums)

    // dir 0: directed(points1=pred, points2=tgt) -> queries = tgt, candidates = pred
    // dir 1: directed(points1=tgt, points2=pred) -> queries = pred, candidates = tgt
    const float* qsrc = (dir == 0) ? tgt  : pred;
    const float* csrc = (dir == 0) ? pred : tgt;
    const float* q0 = qsrc + (size_t)n * (2 * W_IN);
    const float* c0 = csrc + (size_t)n * (2 * W_IN);
    const float* v0 = vis  + (size_t)n * W_IN;

    // ---- Interpolation (align_corners=True linear on last dim) ----
    const float delta = 127.0f / 1023.0f;
    for (int e = tid; e < SIZE; e += NTHREADS) {
        float pos = (float)e * delta;
        int i0 = (int)pos;                       // pos >= 0 -> trunc == floor
        if (i0 > W_IN - 1) i0 = W_IN - 1;
        int i1 = i0 + 1; if (i1 > W_IN - 1) i1 = W_IN - 1;
        float w  = pos - (float)i0;
        float w0 = 1.0f - w;

        float qx = q0[i0]        * w0 + q0[i1]        * w;
        float qy = q0[W_IN + i0] * w0 + q0[W_IN + i1] * w;
        float cx = c0[i0]        * w0 + c0[i1]        * w;
        float cy = c0[W_IN + i0] * w0 + c0[W_IN + i1] * w;
        float mv = v0[i0]        * w0 + v0[i1]        * w;
        if (mv < 0.5f) mv = 0.0f;

        sh_q[e] = make_float2(qx, qy);
        sh_c[e] = make_float2(-cx, -cy);   // negated so dist uses FADD not FSUB pair
        sh_m[e] = mv;
    }
    __syncthreads();

    // ---- Load this thread's 8 queries into registers ----
    float    qx[QPT], qy[QPT];
    unsigned key[QPT];
#pragma unroll
    for (int q = 0; q < QPT; q++) {
        float2 v = sh_q[tid + q * NTHREADS];
        qx[q] = v.x; qy[q] = v.y;
        key[q] = 0xFFFFFFFFu;
    }

    // ---- Main scan: 1024 candidates, packed-key argmin ----
    // key = (float_bits(d) & ~0x3FF) | j : unsigned min => min distance,
    // ties resolve to smallest j (matches jnp.argmin first-occurrence).
#pragma unroll 4
    for (int j = 0; j < SIZE; j++) {
        float2 c = sh_c[j];                         // broadcast LDS.64
#pragma unroll
        for (int q = 0; q < QPT; q++) {
            float dx = qx[q] + c.x;
            float dy = qy[q] + c.y;
            float d  = fmaf(dx, dx, dy * dy);
            unsigned k = (__float_as_uint(d) & 0xFFFFFC00u) | (unsigned)j;
            key[q] = min(key[q], k);                // IMNMX.U32
        }
    }

    // ---- Emit indices + masked min-distance sum ----
    float sum_mse = 0.0f;
#pragma unroll
    for (int q = 0; q < QPT; q++) {
        int i = tid + q * NTHREADS;
        sh_idx[i] = key[q] & 1023u;
        float dmin = __uint_as_float(key[q] & 0xFFFFFC00u);
        sum_mse += dmin * sh_m[i];
    }
    __syncthreads();

    // ---- Index-order penalty + (dir 0) direct error ----
    float sum_ord = 0.0f;
    float sum_dir = 0.0f;
#pragma unroll
    for (int q = 0; q < QPT; q++) {
        int i = tid + q * NTHREADS;
        if (i < SIZE - 1) {
            int   diff = (int)sh_idx[i + 1] - (int)sh_idx[i];
            float nd   = (float)(-diff);
            nd = nd > 0.0f ? nd : 0.0f;             // relu
            sum_ord += nd * nd * sh_m[i];
        }
        if (dir == 0) {
            float2 qv = sh_q[i];
            float2 cv = sh_c[i];
            float dx = qv.x + cv.x;
            float dy = qv.y + cv.y;
            sum_dir += fmaf(dx, dx, dy * dy) * sh_m[i];
        }
    }

    // ---- CTA reduction (deterministic) ----
#pragma unroll
    for (int off = 16; off > 0; off >>= 1) {
        sum_mse += __shfl_down_sync(0xFFFFFFFFu, sum_mse, off);
        sum_ord += __shfl_down_sync(0xFFFFFFFFu, sum_ord, off);
        sum_dir += __shfl_down_sync(0xFFFFFFFFu, sum_dir, off);
    }
    const int warp = tid >> 5, lane = tid & 31;
    if (lane == 0) {
        sh_red[warp * 3 + 0] = sum_mse;
        sh_red[warp * 3 + 1] = sum_ord;
        sh_red[warp * 3 + 2] = sum_dir;
    }
    __syncthreads();
    if (tid == 0) {
        float a = 0.f, b = 0.f, cc = 0.f;
#pragma unroll
        for (int wdx = 0; wdx < NTHREADS / 32; wdx++) {
            a  += sh_red[wdx * 3 + 0];
            b  += sh_red[wdx * 3 + 1];
            cc += sh_red[wdx * 3 + 2];
        }
        g_part[blockIdx.x] = make_float4(a, b, cc, 0.0f);
    }
}

__global__ void finalize_kernel(float* __restrict__ out, int nblocks, int N)
{
    __shared__ float s_mse[256], s_ord[256], s_dir[256];
    const int tid = threadIdx.x;
    float a = 0.f, b = 0.f, c = 0.f;
    for (int i = tid; i < nblocks; i += 256) {
        float4 p = g_part[i];
        a += p.x; b += p.y; c += p.z;
    }
    s_mse[tid] = a; s_ord[tid] = b; s_dir[tid] = c;
    __syncthreads();
    for (int off = 128; off > 0; off >>= 1) {
        if (tid < off) {
            s_mse[tid] += s_mse[tid + off];
            s_ord[tid] += s_ord[tid + off];
            s_dir[tid] += s_dir[tid + off];
        }
        __syncthreads();
    }
    if (tid == 0) {
        float denom_pts = (float)N * (float)SIZE;
        float matched = s_mse[0] / (2.0f * denom_pts)
                      + POINT_ORDER_WEIGHT * s_ord[0] / (2.0f * (float)N * (float)(SIZE - 1));
        float direct  = s_dir[0] / denom_pts;
        out[0] = fminf(matched, direct);
    }
}

extern "C" void kernel_launch(void* const* d_in, const int* in_sizes, int n_in,
                              void* d_out, int out_size)
{
    const float* tgt  = (const float*)d_in[0];
    const float* pred = (const float*)d_in[1];
    const float* vis  = (const float*)d_in[2];
    float* out = (float*)d_out;

    const int N = in_sizes[2] / W_IN;     // 128
    const int nblocks = 2 * N;            // 256 CTAs: (batch, direction)

    chamfer_scan_kernel<<<nblocks, NTHREADS>>>(tgt, pred, vis);
    finalize_kernel<<<1, 256>>>(out, nblocks, N);
}

// round 2
// speedup vs baseline: 1.0468x; 1.0468x over previous
#include <cuda_runtime.h>

// Problem constants (shapes fixed by the benchmark instance)
#define W_IN      128
#define UP_FACTOR 8
#define SIZE      (W_IN * UP_FACTOR)   // 1024 interpolated points
#define NTHREADS  128
#define QPT       (SIZE / NTHREADS)    // 8 queries per thread
#define POINT_ORDER_WEIGHT 0.1f

// Deterministic per-CTA partials: x = sum(min_dist * m), y = sum(order_penalty * m),
// z = sum(direct_err * m) [dir==0 CTAs only]
__device__ float4 g_part[1024];

__global__ __launch_bounds__(NTHREADS)
void chamfer_scan_kernel(const float* __restrict__ tgt,
                         const float* __restrict__ pred,
                         const float* __restrict__ vis)
{
    const int n   = blockIdx.x >> 1;
    const int dir = blockIdx.x & 1;
    const int tid = threadIdx.x;

    __shared__ float2   sh_q[SIZE];     // interpolated queries (points2)
    __shared__ float2   sh_c[SIZE];     // NEGATED interpolated candidates (points1)
    __shared__ float    sh_m[SIZE];     // thresholded mask
    __shared__ unsigned sh_idx[SIZE];   // argmin indices
    __shared__ float    sh_red[12];     // warp partials (4 warps x 3 sums)

    // dir 0: directed(points1=pred, points2=tgt) -> queries = tgt, candidates = pred
    // dir 1: directed(points1=tgt, points2=pred) -> queries = pred, candidates = tgt
    const float* qsrc = (dir == 0) ? tgt  : pred;
    const float* csrc = (dir == 0) ? pred : tgt;
    const float* q0 = qsrc + (size_t)n * (2 * W_IN);
    const float* c0 = csrc + (size_t)n * (2 * W_IN);
    const float* v0 = vis  + (size_t)n * W_IN;

    // ---- Interpolation (align_corners=True linear on last dim) ----
    const float delta = 127.0f / 1023.0f;
    for (int e = tid; e < SIZE; e += NTHREADS) {
        float pos = (float)e * delta;
        int i0 = (int)pos;                       // pos >= 0 -> trunc == floor
        if (i0 > W_IN - 1) i0 = W_IN - 1;
        int i1 = i0 + 1; if (i1 > W_IN - 1) i1 = W_IN - 1;
        float w  = pos - (float)i0;
        float w0 = 1.0f - w;

        float qx = q0[i0]        * w0 + q0[i1]        * w;
        float qy = q0[W_IN + i0] * w0 + q0[W_IN + i1] * w;
        float cx = c0[i0]        * w0 + c0[i1]        * w;
        float cy = c0[W_IN + i0] * w0 + c0[W_IN + i1] * w;
        float mv = v0[i0]        * w0 + v0[i1]        * w;
        if (mv < 0.5f) mv = 0.0f;

        sh_q[e] = make_float2(qx, qy);
        sh_c[e] = make_float2(-cx, -cy);   // negated so dist uses FADD not FSUB pair
        sh_m[e] = mv;
    }
    __syncthreads();

    // ---- Load this thread's 8 queries into registers ----
    float    qx[QPT], qy[QPT];
    unsigned key[QPT];
#pragma unroll
    for (int q = 0; q < QPT; q++) {
        float2 v = sh_q[tid + q * NTHREADS];
        qx[q] = v.x; qy[q] = v.y;
        key[q] = 0xFFFFFFFFu;
    }

    // ---- Main scan: 1024 candidates, packed-key argmin ----
    // key = (float_bits(d) & ~0x3FF) | j : unsigned min => min distance,
    // ties resolve to smallest j (matches jnp.argmin first-occurrence).
#pragma unroll 4
    for (int j = 0; j < SIZE; j++) {
        float2 c = sh_c[j];                         // broadcast LDS.64
#pragma unroll
        for (int q = 0; q < QPT; q++) {
            float dx = qx[q] + c.x;
            float dy = qy[q] + c.y;
            float d  = fmaf(dx, dx, dy * dy);
            unsigned k = (__float_as_uint(d) & 0xFFFFFC00u) | (unsigned)j;
            key[q] = min(key[q], k);                // IMNMX.U32
        }
    }

    // ---- Emit indices + masked min-distance sum ----
    float sum_mse = 0.0f;
#pragma unroll
    for (int q = 0; q < QPT; q++) {
        int i = tid + q * NTHREADS;
        sh_idx[i] = key[q] & 1023u;
        float dmin = __uint_as_float(key[q] & 0xFFFFFC00u);
        sum_mse += dmin * sh_m[i];
    }
    __syncthreads();

    // ---- Index-order penalty + (dir 0) direct error ----
    float sum_ord = 0.0f;
    float sum_dir = 0.0f;
#pragma unroll
    for (int q = 0; q < QPT; q++) {
        int i = tid + q * NTHREADS;
        if (i < SIZE - 1) {
            int   diff = (int)sh_idx[i + 1] - (int)sh_idx[i];
            float nd   = (float)(-diff);
            nd = nd > 0.0f ? nd : 0.0f;             // relu
            sum_ord += nd * nd * sh_m[i];
        }
        if (dir == 0) {
            float2 qv = sh_q[i];
            float2 cv = sh_c[i];
            float dx = qv.x + cv.x;
            float dy = qv.y + cv.y;
            sum_dir += fmaf(dx, dx, dy * dy) * sh_m[i];
        }
    }

    // ---- CTA reduction (deterministic) ----
#pragma unroll
    for (int off = 16; off > 0; off >>= 1) {
        sum_mse += __shfl_down_sync(0xFFFFFFFFu, sum_mse, off);
        sum_ord += __shfl_down_sync(0xFFFFFFFFu, sum_ord, off);
        sum_dir += __shfl_down_sync(0xFFFFFFFFu, sum_dir, off);
    }
    const int warp = tid >> 5, lane = tid & 31;
    if (lane == 0) {
        sh_red[warp * 3 + 0] = sum_mse;
        sh_red[warp * 3 + 1] = sum_ord;
        sh_red[warp * 3 + 2] = sum_dir;
    }
    __syncthreads();
    if (tid == 0) {
        float a = 0.f, b = 0.f, cc = 0.f;
#pragma unroll
        for (int wdx = 0; wdx < NTHREADS / 32; wdx++) {
            a  += sh_red[wdx * 3 + 0];
            b  += sh_red[wdx * 3 + 1];
            cc += sh_red[wdx * 3 + 2];
        }
        g_part[blockIdx.x] = make_float4(a, b, cc, 0.0f);
    }
}

__global__ void finalize_kernel(float* __restrict__ out, int nblocks, int N)
{
    __shared__ float s_mse[256], s_ord[256], s_dir[256];
    const int tid = threadIdx.x;
    float a = 0.f, b = 0.f, c = 0.f;
    for (int i = tid; i < nblocks; i += 256) {
        float4 p = g_part[i];
        a += p.x; b += p.y; c += p.z;
    }
    s_mse[tid] = a; s_ord[tid] = b; s_dir[tid] = c;
    __syncthreads();
    for (int off = 128; off > 0; off >>= 1) {
        if (tid < off) {
            s_mse[tid] += s_mse[tid + off];
            s_ord[tid] += s_ord[tid + off];
            s_dir[tid] += s_dir[tid + off];
        }
        __syncthreads();
    }
    if (tid == 0) {
        float denom_pts = (float)N * (float)SIZE;
        float matched = s_mse[0] / (2.0f * denom_pts)
                      + POINT_ORDER_WEIGHT * s_ord[0] / (2.0f * (float)N * (float)(SIZE - 1));
        float direct  = s_dir[0] / denom_pts;
        out[0] = fminf(matched, direct);
    }
}

extern "C" void kernel_launch(void* const* d_in, const int* in_sizes, int n_in,
                              void* d_out, int out_size)
{
    const float* tgt  = (const float*)d_in[0];
    const float* pred = (const float*)d_in[1];
    const float* vis  = (const float*)d_in[2];
    float* out = (float*)d_out;

    const int N = in_sizes[2] / W_IN;     // 128
    const int nblocks = 2 * N;            // 256 CTAs: (batch, direction)

    chamfer_scan_kernel<<<nblocks, NTHREADS>>>(tgt, pred, vis);
    finalize_kernel<<<1, 256>>>(out, nblocks, N);
}

// round 3
// speedup vs baseline: 1.0487x; 1.0019x over previous
#include <cuda_runtime.h>

// Problem constants (shapes fixed by the benchmark instance)
#define W_IN      128
#define UP_FACTOR 8
#define SIZE      (W_IN * UP_FACTOR)   // 1024 interpolated points
#define NTHREADS  128
#define QPT       (SIZE / NTHREADS)    // 8 queries per thread
#define POINT_ORDER_WEIGHT 0.1f

// Deterministic per-CTA partials: x = sum(min_dist * m), y = sum(order_penalty * m),
// z = sum(direct_err * m) [dir==0 CTAs only]
__device__ float4 g_part[1024];

__global__ __launch_bounds__(NTHREADS)
void chamfer_scan_kernel(const float* __restrict__ tgt,
                         const float* __restrict__ pred,
                         const float* __restrict__ vis)
{
    const int n   = blockIdx.x >> 1;
    const int dir = blockIdx.x & 1;
    const int tid = threadIdx.x;

    __shared__ float2   sh_q[SIZE];     // interpolated queries (points2)
    __shared__ float2   sh_c[SIZE];     // NEGATED interpolated candidates (points1)
    __shared__ float    sh_m[SIZE];     // thresholded mask
    __shared__ unsigned sh_idx[SIZE];   // argmin indices
    __shared__ float    sh_red[12];     // warp partials (4 warps x 3 sums)

    // dir 0: directed(points1=pred, points2=tgt) -> queries = tgt, candidates = pred
    // dir 1: directed(points1=tgt, points2=pred) -> queries = pred, candidates = tgt
    const float* qsrc = (dir == 0) ? tgt  : pred;
    const float* csrc = (dir == 0) ? pred : tgt;
    const float* q0 = qsrc + (size_t)n * (2 * W_IN);
    const float* c0 = csrc + (size_t)n * (2 * W_IN);
    const float* v0 = vis  + (size_t)n * W_IN;

    // ---- Interpolation (align_corners=True linear on last dim) ----
    const float delta = 127.0f / 1023.0f;
    for (int e = tid; e < SIZE; e += NTHREADS) {
        float pos = (float)e * delta;
        int i0 = (int)pos;                       // pos >= 0 -> trunc == floor
        if (i0 > W_IN - 1) i0 = W_IN - 1;
        int i1 = i0 + 1; if (i1 > W_IN - 1) i1 = W_IN - 1;
        float w  = pos - (float)i0;
        float w0 = 1.0f - w;

        float qx = q0[i0]        * w0 + q0[i1]        * w;
        float qy = q0[W_IN + i0] * w0 + q0[W_IN + i1] * w;
        float cx = c0[i0]        * w0 + c0[i1]        * w;
        float cy = c0[W_IN + i0] * w0 + c0[W_IN + i1] * w;
        float mv = v0[i0]        * w0 + v0[i1]        * w;
        if (mv < 0.5f) mv = 0.0f;

        sh_q[e] = make_float2(qx, qy);
        sh_c[e] = make_float2(-cx, -cy);   // negated so dist uses FADD not FSUB pair
        sh_m[e] = mv;
    }
    __syncthreads();

    // ---- Load this thread's 8 queries into registers ----
    float    qx[QPT], qy[QPT];
    unsigned key[QPT];
#pragma unroll
    for (int q = 0; q < QPT; q++) {
        float2 v = sh_q[tid + q * NTHREADS];
        qx[q] = v.x; qy[q] = v.y;
        key[q] = 0xFFFFFFFFu;
    }

    // ---- Main scan: 1024 candidates, packed-key argmin ----
    // key = (float_bits(d) & ~0x3FF) | j : unsigned min => min distance,
    // ties resolve to smallest j (matches jnp.argmin first-occurrence).
#pragma unroll 4
    for (int j = 0; j < SIZE; j++) {
        float2 c = sh_c[j];                         // broadcast LDS.64
#pragma unroll
        for (int q = 0; q < QPT; q++) {
            float dx = qx[q] + c.x;
            float dy = qy[q] + c.y;
            float d  = fmaf(dx, dx, dy * dy);
            unsigned k = (__float_as_uint(d) & 0xFFFFFC00u) | (unsigned)j;
            key[q] = min(key[q], k);                // IMNMX.U32
        }
    }

    // ---- Emit indices + masked min-distance sum ----
    float sum_mse = 0.0f;
#pragma unroll
    for (int q = 0; q < QPT; q++) {
        int i = tid + q * NTHREADS;
        sh_idx[i] = key[q] & 1023u;
        float dmin = __uint_as_float(key[q] & 0xFFFFFC00u);
        sum_mse += dmin * sh_m[i];
    }
    __syncthreads();

    // ---- Index-order penalty + (dir 0) direct error ----
    float sum_ord = 0.0f;
    float sum_dir = 0.0f;
#pragma unroll
    for (int q = 0; q < QPT; q++) {
        int i = tid + q * NTHREADS;
        if (i < SIZE - 1) {
            int   diff = (int)sh_idx[i + 1] - (int)sh_idx[i];
            float nd   = (float)(-diff);
            nd = nd > 0.0f ? nd : 0.0f;             // relu
            sum_ord += nd * nd * sh_m[i];
        }
        if (dir == 0) {
            float2 qv = sh_q[i];
            float2 cv = sh_c[i];
            float dx = qv.x + cv.x;
            float dy = qv.y + cv.y;
            sum_dir += fmaf(dx, dx, dy * dy) * sh_m[i];
        }
    }

    // ---- CTA reduction (deterministic) ----
#pragma unroll
    for (int off = 16; off > 0; off >>= 1) {
        sum_mse += __shfl_down_sync(0xFFFFFFFFu, sum_mse, off);
        sum_ord += __shfl_down_sync(0xFFFFFFFFu, sum_ord, off);
        sum_dir += __shfl_down_sync(0xFFFFFFFFu, sum_dir, off);
    }
    const int warp = tid >> 5, lane = tid & 31;
    if (lane == 0) {
        sh_red[warp * 3 + 0] = sum_mse;
        sh_red[warp * 3 + 1] = sum_ord;
        sh_red[warp * 3 + 2] = sum_dir;
    }
    __syncthreads();
    if (tid == 0) {
        float a = 0.f, b = 0.f, cc = 0.f;
#pragma unroll
        for (int wdx = 0; wdx < NTHREADS / 32; wdx++) {
            a  += sh_red[wdx * 3 + 0];
            b  += sh_red[wdx * 3 + 1];
            cc += sh_red[wdx * 3 + 2];
        }
        g_part[blockIdx.x] = make_float4(a, b, cc, 0.0f);
    }
}

__global__ void finalize_kernel(float* __restrict__ out, int nblocks, int N)
{
    __shared__ float s_mse[256], s_ord[256], s_dir[256];
    const int tid = threadIdx.x;
    float a = 0.f, b = 0.f, c = 0.f;
    for (int i = tid; i < nblocks; i += 256) {
        float4 p = g_part[i];
        a += p.x; b += p.y; c += p.z;
    }
    s_mse[tid] = a; s_ord[tid] = b; s_dir[tid] = c;
    __syncthreads();
    for (int off = 128; off > 0; off >>= 1) {
        if (tid < off) {
            s_mse[tid] += s_mse[tid + off];
            s_ord[tid] += s_ord[tid + off];
            s_dir[tid] += s_dir[tid + off];
        }
        __syncthreads();
    }
    if (tid == 0) {
        float denom_pts = (float)N * (float)SIZE;
        float matched = s_mse[0] / (2.0f * denom_pts)
                      + POINT_ORDER_WEIGHT * s_ord[0] / (2.0f * (float)N * (float)(SIZE - 1));
        float direct  = s_dir[0] / denom_pts;
        out[0] = fminf(matched, direct);
    }
}

extern "C" void kernel_launch(void* const* d_in, const int* in_sizes, int n_in,
                              void* d_out, int out_size)
{
    const float* tgt  = (const float*)d_in[0];
    const float* pred = (const float*)d_in[1];
    const float* vis  = (const float*)d_in[2];
    float* out = (float*)d_out;

    const int N = in_sizes[2] / W_IN;     // 128
    const int nblocks = 2 * N;            // 256 CTAs: (batch, direction)

    chamfer_scan_kernel<<<nblocks, NTHREADS>>>(tgt, pred, vis);
    finalize_kernel<<<1, 256>>>(out, nblocks, N);
}

// round 4
// speedup vs baseline: 1.2524x; 1.1942x over previous
#include <cuda_runtime.h>

// Problem constants (shapes fixed by the benchmark instance)
#define W_IN      128
#define UP_FACTOR 8
#define SIZE      (W_IN * UP_FACTOR)   // 1024 interpolated points
#define NTHREADS  128
#define QPT       (SIZE / NTHREADS)    // 8 queries per thread
#define NPAIR     (QPT / 2)            // 4 packed query pairs per thread
#define POINT_ORDER_WEIGHT 0.1f

typedef unsigned long long u64;

// ---- Blackwell packed f32x2 helpers (sm_103a) ----
__device__ __forceinline__ u64 pk2(float lo, float hi) {
    u64 r; asm("mov.b64 %0, {%1, %2};" : "=l"(r) : "f"(lo), "f"(hi)); return r;
}
__device__ __forceinline__ u64 add2(u64 a, u64 b) {
    u64 r; asm("add.rn.f32x2 %0, %1, %2;" : "=l"(r) : "l"(a), "l"(b)); return r;
}
__device__ __forceinline__ u64 mul2(u64 a, u64 b) {
    u64 r; asm("mul.rn.f32x2 %0, %1, %2;" : "=l"(r) : "l"(a), "l"(b)); return r;
}
__device__ __forceinline__ u64 fma2(u64 a, u64 b, u64 c) {
    u64 r; asm("fma.rn.f32x2 %0, %1, %2, %3;" : "=l"(r) : "l"(a), "l"(b), "l"(c)); return r;
}
__device__ __forceinline__ void unpk2(u64 v, unsigned &lo, unsigned &hi) {
    asm("mov.b64 {%0, %1}, %2;" : "=r"(lo), "=r"(hi) : "l"(v));
}

// Deterministic per-CTA partials: x = sum(min_dist * m), y = sum(order_penalty * m),
// z = sum(direct_err * m) [dir==0 CTAs only]
__device__ float4 g_part[1024];

__global__ __launch_bounds__(NTHREADS)
void chamfer_scan_kernel(const float* __restrict__ tgt,
                         const float* __restrict__ pred,
                         const float* __restrict__ vis)
{
    const int n   = blockIdx.x >> 1;
    const int dir = blockIdx.x & 1;
    const int tid = threadIdx.x;

    __shared__ float2      sh_q[SIZE];    // interpolated queries (points2)
    __shared__ ulonglong2  sh_cc[SIZE];   // candidate j: {(-cx,-cx), (-cy,-cy)} packed, 16B
    __shared__ float       sh_m[SIZE];    // thresholded mask
    __shared__ unsigned    sh_idx[SIZE];  // argmin indices
    __shared__ float       sh_red[12];    // warp partials (4 warps x 3 sums)

    // dir 0: directed(points1=pred, points2=tgt) -> queries = tgt, candidates = pred
    // dir 1: directed(points1=tgt, points2=pred) -> queries = pred, candidates = tgt
    const float* qsrc = (dir == 0) ? tgt  : pred;
    const float* csrc = (dir == 0) ? pred : tgt;
    const float* q0 = qsrc + (size_t)n * (2 * W_IN);
    const float* c0 = csrc + (size_t)n * (2 * W_IN);
    const float* v0 = vis  + (size_t)n * W_IN;

    // ---- Interpolation (align_corners=True linear on last dim) ----
    const float delta = 127.0f / 1023.0f;
    for (int e = tid; e < SIZE; e += NTHREADS) {
        float pos = (float)e * delta;
        int i0 = (int)pos;                       // pos >= 0 -> trunc == floor
        if (i0 > W_IN - 1) i0 = W_IN - 1;
        int i1 = i0 + 1; if (i1 > W_IN - 1) i1 = W_IN - 1;
        float w  = pos - (float)i0;
        float w0 = 1.0f - w;

        float qx = q0[i0]        * w0 + q0[i1]        * w;
        float qy = q0[W_IN + i0] * w0 + q0[W_IN + i1] * w;
        float cx = c0[i0]        * w0 + c0[i1]        * w;
        float cy = c0[W_IN + i0] * w0 + c0[W_IN + i1] * w;
        float mv = v0[i0]        * w0 + v0[i1]        * w;
        if (mv < 0.5f) mv = 0.0f;

        sh_q[e] = make_float2(qx, qy);
        // negated + duplicated so the scan uses packed FADD against query pairs
        sh_cc[e].x = pk2(-cx, -cx);
        sh_cc[e].y = pk2(-cy, -cy);
        sh_m[e] = mv;
    }
    __syncthreads();

    // ---- Load this thread's 8 queries into packed register pairs ----
    // pair p covers queries (2p, 2p+1) -> global indices tid + 2p*128, tid + (2p+1)*128
    u64      qx2[NPAIR], qy2[NPAIR];
    unsigned keyL[NPAIR], keyH[NPAIR];
#pragma unroll
    for (int p = 0; p < NPAIR; p++) {
        float2 a = sh_q[tid + (2 * p) * NTHREADS];
        float2 b = sh_q[tid + (2 * p + 1) * NTHREADS];
        qx2[p] = pk2(a.x, b.x);
        qy2[p] = pk2(a.y, b.y);
        keyL[p] = 0xFFFFFFFFu;
        keyH[p] = 0xFFFFFFFFu;
    }

    // ---- Main scan: 1024 candidates, packed f32x2 distances + packed-key argmin ----
    // d = fma(dx, dx, dy*dy)  (elementwise rounding identical to scalar fmaf version)
    // key = (float_bits(d) & ~0x3FF) | j : unsigned min => min distance,
    // ties resolve to smallest j (matches jnp.argmin first-occurrence).
#pragma unroll 4
    for (int j = 0; j < SIZE; j++) {
        ulonglong2 cc = sh_cc[j];                 // single LDS.128 broadcast
        unsigned jj = (unsigned)j;
#pragma unroll
        for (int p = 0; p < NPAIR; p++) {
            u64 dx = add2(qx2[p], cc.x);
            u64 dy = add2(qy2[p], cc.y);
            u64 s  = mul2(dy, dy);
            u64 d  = fma2(dx, dx, s);
            unsigned dl, dh; unpk2(d, dl, dh);
            unsigned kl = (dl & 0xFFFFFC00u) | jj;   // single LOP3
            unsigned kh = (dh & 0xFFFFFC00u) | jj;
            keyL[p] = min(keyL[p], kl);              // IMNMX.U32
            keyH[p] = min(keyH[p], kh);
        }
    }

    // ---- Emit indices + masked min-distance sum ----
    float sum_mse = 0.0f;
#pragma unroll
    for (int p = 0; p < NPAIR; p++) {
        int iL = tid + (2 * p) * NTHREADS;
        int iH = tid + (2 * p + 1) * NTHREADS;
        sh_idx[iL] = keyL[p] & 1023u;
        sh_idx[iH] = keyH[p] & 1023u;
        sum_mse += __uint_as_float(keyL[p] & 0xFFFFFC00u) * sh_m[iL];
        sum_mse += __uint_as_float(keyH[p] & 0xFFFFFC00u) * sh_m[iH];
    }
    __syncthreads();

    // ---- Index-order penalty + (dir 0) direct error ----
    float sum_ord = 0.0f;
    float sum_dir = 0.0f;
#pragma unroll
    for (int q = 0; q < QPT; q++) {
        int i = tid + q * NTHREADS;
        if (i < SIZE - 1) {
            int   diff = (int)sh_idx[i + 1] - (int)sh_idx[i];
            float nd   = (float)(-diff);
            nd = nd > 0.0f ? nd : 0.0f;             // relu
            sum_ord += nd * nd * sh_m[i];
        }
        if (dir == 0) {
            float2 qv = sh_q[i];
            unsigned cxl, cxh, cyl, cyh;
            unpk2(sh_cc[i].x, cxl, cxh);
            unpk2(sh_cc[i].y, cyl, cyh);
            float dx = qv.x + __uint_as_float(cxl);  // qx + (-cx)
            float dy = qv.y + __uint_as_float(cyl);
            sum_dir += fmaf(dx, dx, dy * dy) * sh_m[i];
        }
    }

    // ---- CTA reduction (deterministic) ----
#pragma unroll
    for (int off = 16; off > 0; off >>= 1) {
        sum_mse += __shfl_down_sync(0xFFFFFFFFu, sum_mse, off);
        sum_ord += __shfl_down_sync(0xFFFFFFFFu, sum_ord, off);
        sum_dir += __shfl_down_sync(0xFFFFFFFFu, sum_dir, off);
    }
    const int warp = tid >> 5, lane = tid & 31;
    if (lane == 0) {
        sh_red[warp * 3 + 0] = sum_mse;
        sh_red[warp * 3 + 1] = sum_ord;
        sh_red[warp * 3 + 2] = sum_dir;
    }
    __syncthreads();
    if (tid == 0) {
        float a = 0.f, b = 0.f, cc = 0.f;
#pragma unroll
        for (int wdx = 0; wdx < NTHREADS / 32; wdx++) {
            a  += sh_red[wdx * 3 + 0];
            b  += sh_red[wdx * 3 + 1];
            cc += sh_red[wdx * 3 + 2];
        }
        g_part[blockIdx.x] = make_float4(a, b, cc, 0.0f);
    }
}

__global__ void finalize_kernel(float* __restrict__ out, int nblocks, int N)
{
    __shared__ float s_mse[256], s_ord[256], s_dir[256];
    const int tid = threadIdx.x;
    float a = 0.f, b = 0.f, c = 0.f;
    for (int i = tid; i < nblocks; i += 256) {
        float4 p = g_part[i];
        a += p.x; b += p.y; c += p.z;
    }
    s_mse[tid] = a; s_ord[tid] = b; s_dir[tid] = c;
    __syncthreads();
    for (int off = 128; off > 0; off >>= 1) {
        if (tid < off) {
            s_mse[tid] += s_mse[tid + off];
            s_ord[tid] += s_ord[tid + off];
            s_dir[tid] += s_dir[tid + off];
        }
        __syncthreads();
    }
    if (tid == 0) {
        float denom_pts = (float)N * (float)SIZE;
        float matched = s_mse[0] / (2.0f * denom_pts)
                      + POINT_ORDER_WEIGHT * s_ord[0] / (2.0f * (float)N * (float)(SIZE - 1));
        float direct  = s_dir[0] / denom_pts;
        out[0] = fminf(matched, direct);
    }
}

extern "C" void kernel_launch(void* const* d_in, const int* in_sizes, int n_in,
                              void* d_out, int out_size)
{
    const float* tgt  = (const float*)d_in[0];
    const float* pred = (const float*)d_in[1];
    const float* vis  = (const float*)d_in[2];
    float* out = (float*)d_out;

    const int N = in_sizes[2] / W_IN;     // 128
    const int nblocks = 2 * N;            // 256 CTAs: (batch, direction)

    chamfer_scan_kernel<<<nblocks, NTHREADS>>>(tgt, pred, vis);
    finalize_kernel<<<1, 256>>>(out, nblocks, N);
}

// round 5
// speedup vs baseline: 1.2593x; 1.0055x over previous
#include <cuda_runtime.h>

// Problem constants (shapes fixed by the benchmark instance)
#define W_IN      128
#define UP_FACTOR 8
#define SIZE      (W_IN * UP_FACTOR)   // 1024 interpolated points
#define NTHREADS  128
#define QPT       (SIZE / NTHREADS)    // 8 queries per thread
#define NPAIR     (QPT / 2)            // 4 packed query pairs per thread
#define POINT_ORDER_WEIGHT 0.1f

typedef unsigned long long u64;

// ---- Blackwell packed f32x2 helpers (sm_103a) ----
__device__ __forceinline__ u64 pk2(float lo, float hi) {
    u64 r; asm("mov.b64 %0, {%1, %2};" : "=l"(r) : "f"(lo), "f"(hi)); return r;
}
__device__ __forceinline__ u64 add2(u64 a, u64 b) {
    u64 r; asm("add.rn.f32x2 %0, %1, %2;" : "=l"(r) : "l"(a), "l"(b)); return r;
}
__device__ __forceinline__ u64 mul2(u64 a, u64 b) {
    u64 r; asm("mul.rn.f32x2 %0, %1, %2;" : "=l"(r) : "l"(a), "l"(b)); return r;
}
__device__ __forceinline__ u64 fma2(u64 a, u64 b, u64 c) {
    u64 r; asm("fma.rn.f32x2 %0, %1, %2, %3;" : "=l"(r) : "l"(a), "l"(b), "l"(c)); return r;
}
__device__ __forceinline__ void unpk2(u64 v, unsigned &lo, unsigned &hi) {
    asm("mov.b64 {%0, %1}, %2;" : "=r"(lo), "=r"(hi) : "l"(v));
}

// Deterministic per-CTA partials: x = sum(min_dist * m), y = sum(order_penalty * m),
// z = sum(direct_err * m) [dir==0 CTAs only]
__device__ float4 g_part[1024];

__global__ __launch_bounds__(NTHREADS)
void chamfer_scan_kernel(const float* __restrict__ tgt,
                         const float* __restrict__ pred,
                         const float* __restrict__ vis)
{
    const int n   = blockIdx.x >> 1;
    const int dir = blockIdx.x & 1;
    const int tid = threadIdx.x;

    __shared__ float2      sh_q[SIZE];    // interpolated queries (points2)
    __shared__ ulonglong2  sh_cc[SIZE];   // candidate j: {(-cx,-cx), (-cy,-cy)} packed, 16B
    __shared__ float       sh_m[SIZE];    // thresholded mask
    __shared__ unsigned    sh_idx[SIZE];  // argmin indices
    __shared__ float       sh_red[12];    // warp partials (4 warps x 3 sums)

    // dir 0: directed(points1=pred, points2=tgt) -> queries = tgt, candidates = pred
    // dir 1: directed(points1=tgt, points2=pred) -> queries = pred, candidates = tgt
    const float* qsrc = (dir == 0) ? tgt  : pred;
    const float* csrc = (dir == 0) ? pred : tgt;
    const float* q0 = qsrc + (size_t)n * (2 * W_IN);
    const float* c0 = csrc + (size_t)n * (2 * W_IN);
    const float* v0 = vis  + (size_t)n * W_IN;

    // ---- Interpolation (align_corners=True linear on last dim) ----
    const float delta = 127.0f / 1023.0f;
    for (int e = tid; e < SIZE; e += NTHREADS) {
        float pos = (float)e * delta;
        int i0 = (int)pos;                       // pos >= 0 -> trunc == floor
        if (i0 > W_IN - 1) i0 = W_IN - 1;
        int i1 = i0 + 1; if (i1 > W_IN - 1) i1 = W_IN - 1;
        float w  = pos - (float)i0;
        float w0 = 1.0f - w;

        float qx = q0[i0]        * w0 + q0[i1]        * w;
        float qy = q0[W_IN + i0] * w0 + q0[W_IN + i1] * w;
        float cx = c0[i0]        * w0 + c0[i1]        * w;
        float cy = c0[W_IN + i0] * w0 + c0[W_IN + i1] * w;
        float mv = v0[i0]        * w0 + v0[i1]        * w;
        if (mv < 0.5f) mv = 0.0f;

        sh_q[e] = make_float2(qx, qy);
        // negated + duplicated so the scan uses packed FADD against query pairs
        sh_cc[e].x = pk2(-cx, -cx);
        sh_cc[e].y = pk2(-cy, -cy);
        sh_m[e] = mv;
    }
    __syncthreads();

    // ---- Load this thread's 8 queries into packed register pairs ----
    // pair p covers queries (2p, 2p+1) -> global indices tid + 2p*128, tid + (2p+1)*128
    u64      qx2[NPAIR], qy2[NPAIR];
    unsigned keyL[NPAIR], keyH[NPAIR];
#pragma unroll
    for (int p = 0; p < NPAIR; p++) {
        float2 a = sh_q[tid + (2 * p) * NTHREADS];
        float2 b = sh_q[tid + (2 * p + 1) * NTHREADS];
        qx2[p] = pk2(a.x, b.x);
        qy2[p] = pk2(a.y, b.y);
        keyL[p] = 0xFFFFFFFFu;
        keyH[p] = 0xFFFFFFFFu;
    }

    // ---- Main scan: 1024 candidates, packed f32x2 distances + packed-key argmin ----
    // d = fma(dx, dx, dy*dy)  (elementwise rounding identical to scalar fmaf version)
    // key = (float_bits(d) & ~0x3FF) | j : unsigned min => min distance,
    // ties resolve to smallest j (matches jnp.argmin first-occurrence).
#pragma unroll 4
    for (int j = 0; j < SIZE; j++) {
        ulonglong2 cc = sh_cc[j];                 // single LDS.128 broadcast
        unsigned jj = (unsigned)j;
#pragma unroll
        for (int p = 0; p < NPAIR; p++) {
            u64 dx = add2(qx2[p], cc.x);
            u64 dy = add2(qy2[p], cc.y);
            u64 s  = mul2(dy, dy);
            u64 d  = fma2(dx, dx, s);
            unsigned dl, dh; unpk2(d, dl, dh);
            unsigned kl = (dl & 0xFFFFFC00u) | jj;   // single LOP3
            unsigned kh = (dh & 0xFFFFFC00u) | jj;
            keyL[p] = min(keyL[p], kl);              // IMNMX.U32
            keyH[p] = min(keyH[p], kh);
        }
    }

    // ---- Emit indices + masked min-distance sum ----
    float sum_mse = 0.0f;
#pragma unroll
    for (int p = 0; p < NPAIR; p++) {
        int iL = tid + (2 * p) * NTHREADS;
        int iH = tid + (2 * p + 1) * NTHREADS;
        sh_idx[iL] = keyL[p] & 1023u;
        sh_idx[iH] = keyH[p] & 1023u;
        sum_mse += __uint_as_float(keyL[p] & 0xFFFFFC00u) * sh_m[iL];
        sum_mse += __uint_as_float(keyH[p] & 0xFFFFFC00u) * sh_m[iH];
    }
    __syncthreads();

    // ---- Index-order penalty + (dir 0) direct error ----
    float sum_ord = 0.0f;
    float sum_dir = 0.0f;
#pragma unroll
    for (int q = 0; q < QPT; q++) {
        int i = tid + q * NTHREADS;
        if (i < SIZE - 1) {
            int   diff = (int)sh_idx[i + 1] - (int)sh_idx[i];
            float nd   = (float)(-diff);
            nd = nd > 0.0f ? nd : 0.0f;             // relu
            sum_ord += nd * nd * sh_m[i];
        }
        if (dir == 0) {
            float2 qv = sh_q[i];
            unsigned cxl, cxh, cyl, cyh;
            unpk2(sh_cc[i].x, cxl, cxh);
            unpk2(sh_cc[i].y, cyl, cyh);
            float dx = qv.x + __uint_as_float(cxl);  // qx + (-cx)
            float dy = qv.y + __uint_as_float(cyl);
            sum_dir += fmaf(dx, dx, dy * dy) * sh_m[i];
        }
    }

    // ---- CTA reduction (deterministic) ----
#pragma unroll
    for (int off = 16; off > 0; off >>= 1) {
        sum_mse += __shfl_down_sync(0xFFFFFFFFu, sum_mse, off);
        sum_ord += __shfl_down_sync(0xFFFFFFFFu, sum_ord, off);
        sum_dir += __shfl_down_sync(0xFFFFFFFFu, sum_dir, off);
    }
    const int warp = tid >> 5, lane = tid & 31;
    if (lane == 0) {
        sh_red[warp * 3 + 0] = sum_mse;
        sh_red[warp * 3 + 1] = sum_ord;
        sh_red[warp * 3 + 2] = sum_dir;
    }
    __syncthreads();
    if (tid == 0) {
        float a = 0.f, b = 0.f, cc = 0.f;
#pragma unroll
        for (int wdx = 0; wdx < NTHREADS / 32; wdx++) {
            a  += sh_red[wdx * 3 + 0];
            b  += sh_red[wdx * 3 + 1];
            cc += sh_red[wdx * 3 + 2];
        }
        g_part[blockIdx.x] = make_float4(a, b, cc, 0.0f);
    }
}

__global__ void finalize_kernel(float* __restrict__ out, int nblocks, int N)
{
    __shared__ float s_mse[256], s_ord[256], s_dir[256];
    const int tid = threadIdx.x;
    float a = 0.f, b = 0.f, c = 0.f;
    for (int i = tid; i < nblocks; i += 256) {
        float4 p = g_part[i];
        a += p.x; b += p.y; c += p.z;
    }
    s_mse[tid] = a; s_ord[tid] = b; s_dir[tid] = c;
    __syncthreads();
    for (int off = 128; off > 0; off >>= 1) {
        if (tid < off) {
            s_mse[tid] += s_mse[tid + off];
            s_ord[tid] += s_ord[tid + off];
            s_dir[tid] += s_dir[tid + off];
        }
        __syncthreads();
    }
    if (tid == 0) {
        float denom_pts = (float)N * (float)SIZE;
        float matched = s_mse[0] / (2.0f * denom_pts)
                      + POINT_ORDER_WEIGHT * s_ord[0] / (2.0f * (float)N * (float)(SIZE - 1));
        float direct  = s_dir[0] / denom_pts;
        out[0] = fminf(matched, direct);
    }
}

extern "C" void kernel_launch(void* const* d_in, const int* in_sizes, int n_in,
                              void* d_out, int out_size)
{
    const float* tgt  = (const float*)d_in[0];
    const float* pred = (const float*)d_in[1];
    const float* vis  = (const float*)d_in[2];
    float* out = (float*)d_out;

    const int N = in_sizes[2] / W_IN;     // 128
    const int nblocks = 2 * N;            // 256 CTAs: (batch, direction)

    chamfer_scan_kernel<<<nblocks, NTHREADS>>>(tgt, pred, vis);
    finalize_kernel<<<1, 256>>>(out, nblocks, N);
}